// round 15
// baseline (speedup 1.0000x reference)
#include <cuda_runtime.h>
#include <cuda_fp16.h>
#include <math.h>
#include <stdint.h>

// Problem constants
#define M_ROWS 16384            // b * h * w = 4*64*64
#define C_DIM  180
#define KP     192              // padded K for fp16 GEMM operands (12*16)
#define NHEAD  6
#define DHEAD  30
#define WS     16
#define OWS    24
#define NKEY   (OWS*OWS)        // 576
#define NQ     (WS*WS)          // 256
#define KC     64               // keys per attention chunk

#define HSTRIDE 56              // looped-GEMM smem row stride (halves)
#define GSTR2   200             // single-shot GEMM smem row stride (halves)
#define KSTR    40              // attention K smem stride (halves)
#define VSTR    72              // attention V^T smem stride (halves)
#define ABUF_H (128 * HSTRIDE)
#define WBUF_H (64 * HSTRIDE)
#define FULL_SMEM ((64 * GSTR2 + 64 * GSTR2) * 2)    // 51200 bytes (BM=64)

// weight16 segment offsets (halves)
#define W_KV   0
#define W_Q    (W_KV + 360 * KP)
#define W_PROJ (W_Q + 180 * KP)
#define W_FC1  (W_PROJ + 180 * KP)
#define W_FC2  (W_FC1 + 720 * KP)
#define W_TOT  (W_FC2 + 180 * 720)

// prep kernel block ranges
#define LN_BLKS   (M_ROWS / 8)                         // 2048 per tensor
#define BIAS_BLKS ((NHEAD * NKEY * NQ + 255) / 256)    // 3456
#define CONV_BLKS ((W_TOT + 255) / 256)                // 1587
#define PREP_BLKS (2 * LN_BLKS + BIAS_BLKS + CONV_BLKS)

// ---------------- scratch (device globals; no allocation allowed) -----------
__device__ __half g_xn_h [M_ROWS * KP];
__device__ __half g_yn_h [M_ROWS * KP];
__device__ __half g_at_h [M_ROWS * KP];
__device__ __half g_xn2_h[M_ROWS * KP];
__device__ __half g_h1_h [M_ROWS * 4 * C_DIM];
__device__ __half g_w16  [W_TOT];
__device__ __half g_kv_h [M_ROWS * 2 * C_DIM];
__device__ __half g_q_h  [M_ROWS * C_DIM];
__device__ __half g_xo_h [M_ROWS * C_DIM];
// bias in C-fragment order: [h][k8 (72)][q16 (16)][lane (32)][4]
__device__ float  g_bias [NHEAD * NKEY * NQ];

// ---------------- mma / ldmatrix / async helpers ------------------------------
__device__ __forceinline__ void mma_f16(float c[4], const uint32_t a[4], const uint32_t b[2]) {
    asm volatile(
        "mma.sync.aligned.m16n8k16.row.col.f32.f16.f16.f32 "
        "{%0,%1,%2,%3},{%4,%5,%6,%7},{%8,%9},{%0,%1,%2,%3};"
        : "+f"(c[0]), "+f"(c[1]), "+f"(c[2]), "+f"(c[3])
        : "r"(a[0]), "r"(a[1]), "r"(a[2]), "r"(a[3]), "r"(b[0]), "r"(b[1]));
}

__device__ __forceinline__ void ldsm_x4(uint32_t r[4], uint32_t addr) {
    asm volatile("ldmatrix.sync.aligned.m8n8.x4.shared.b16 {%0,%1,%2,%3}, [%4];"
                 : "=r"(r[0]), "=r"(r[1]), "=r"(r[2]), "=r"(r[3]) : "r"(addr));
}

__device__ __forceinline__ uint32_t smem_u32(const void* p) {
    return (uint32_t)__cvta_generic_to_shared(p);
}

__device__ __forceinline__ void cp_async16h(__half* smem_dst, const __half* gmem_src, bool pred) {
    uint32_t s = smem_u32(smem_dst);
    int sz = pred ? 16 : 0;
    asm volatile("cp.async.cg.shared.global [%0], [%1], 16, %2;"
                 :: "r"(s), "l"(gmem_src), "r"(sz));
}
__device__ __forceinline__ void cp_commit() {
    asm volatile("cp.async.commit_group;");
}
template<int N>
__device__ __forceinline__ void cp_wait() {
    asm volatile("cp.async.wait_group %0;" :: "n"(N));
}

__device__ __forceinline__ uint32_t pack_h2(float lo, float hi) {
    __half2 h = __floats2half2_rn(lo, hi);
    return *(uint32_t*)&h;
}

// ---------------- LayerNorm row bodies ----------------------------------------
__device__ __forceinline__ void ln_row(
    const float* __restrict__ xr, const float* __restrict__ g,
    const float* __restrict__ b, __half* __restrict__ orow)
{
    int lane = threadIdx.x & 31;
    float v[6];
    float s = 0.f;
    #pragma unroll
    for (int i = 0; i < 6; i++) {
        int idx = lane + 32 * i;
        v[i] = (idx < C_DIM) ? xr[idx] : 0.f;
        s += v[i];
    }
    #pragma unroll
    for (int o = 16; o > 0; o >>= 1) s += __shfl_xor_sync(0xffffffffu, s, o);
    float mean = s * (1.f / C_DIM);
    float s2 = 0.f;
    #pragma unroll
    for (int i = 0; i < 6; i++) {
        int idx = lane + 32 * i;
        float d = (idx < C_DIM) ? (v[i] - mean) : 0.f;
        s2 += d * d;
    }
    #pragma unroll
    for (int o = 16; o > 0; o >>= 1) s2 += __shfl_xor_sync(0xffffffffu, s2, o);
    float r = rsqrtf(s2 * (1.f / C_DIM) + 1e-5f);
    #pragma unroll
    for (int i = 0; i < 6; i++) {
        int idx = lane + 32 * i;
        float res = (idx < C_DIM) ? (v[i] - mean) * r * g[idx] + b[idx] : 0.f;
        orow[idx] = __float2half(res);
    }
}

__device__ __forceinline__ void ln_row_h(
    const __half* __restrict__ xr, const float* __restrict__ g,
    const float* __restrict__ b, __half* __restrict__ orow)
{
    int lane = threadIdx.x & 31;
    float v[6];
    float s = 0.f;
    #pragma unroll
    for (int i = 0; i < 6; i++) {
        int idx = lane + 32 * i;
        v[i] = (idx < C_DIM) ? __half2float(xr[idx]) : 0.f;
        s += v[i];
    }
    #pragma unroll
    for (int o = 16; o > 0; o >>= 1) s += __shfl_xor_sync(0xffffffffu, s, o);
    float mean = s * (1.f / C_DIM);
    float s2 = 0.f;
    #pragma unroll
    for (int i = 0; i < 6; i++) {
        int idx = lane + 32 * i;
        float d = (idx < C_DIM) ? (v[i] - mean) : 0.f;
        s2 += d * d;
    }
    #pragma unroll
    for (int o = 16; o > 0; o >>= 1) s2 += __shfl_xor_sync(0xffffffffu, s2, o);
    float r = rsqrtf(s2 * (1.f / C_DIM) + 1e-5f);
    #pragma unroll
    for (int i = 0; i < 6; i++) {
        int idx = lane + 32 * i;
        float res = (idx < C_DIM) ? (v[i] - mean) * r * g[idx] + b[idx] : 0.f;
        orow[idx] = __float2half(res);
    }
}

// ---------------- fused prologue: LN(x), LN(y), bias table, weight conv ------
__global__ void __launch_bounds__(256) prep_kernel(
    const float* __restrict__ x, const float* __restrict__ y,
    const float* __restrict__ n1g, const float* __restrict__ n1b,
    __half* __restrict__ xn, __half* __restrict__ yn,
    const int* __restrict__ rpi, const float* __restrict__ rpb,
    float* __restrict__ biasF,
    const float* __restrict__ kv_w, const float* __restrict__ q_w,
    const float* __restrict__ proj_w, const float* __restrict__ fc1_w,
    const float* __restrict__ fc2_w, __half* __restrict__ w16)
{
    int blk = blockIdx.x;
    if (blk < 2 * LN_BLKS) {
        const float* src = (blk < LN_BLKS) ? x : y;
        __half* dst      = (blk < LN_BLKS) ? xn : yn;
        int base = (blk < LN_BLKS) ? blk : blk - LN_BLKS;
        int row = base * 8 + (threadIdx.x >> 5);
        ln_row(src + (size_t)row * C_DIM, n1g, n1b, dst + (size_t)row * KP);
        return;
    }
    blk -= 2 * LN_BLKS;
    if (blk < BIAS_BLKS) {
        int idx = blk * 256 + threadIdx.x;
        if (idx >= NHEAD * NKEY * NQ) return;
        int u    = idx & 3;
        int lane = (idx >> 2) & 31;
        int qblk = (idx >> 7) & 15;
        int rest = idx >> 11;          // h*72 + k8
        int k8   = rest % 72;
        int h    = rest / 72;
        int gid = lane >> 2, tig = lane & 3;
        int qq = qblk * 16 + gid + ((u & 2) ? 8 : 0);
        int kk = k8 * 8 + 2 * tig + (u & 1);
        biasF[idx] = rpb[rpi[qq * NKEY + kk] * NHEAD + h];
        return;
    }
    blk -= BIAS_BLKS;
    {
        int idx = blk * 256 + threadIdx.x;
        if (idx >= W_TOT) return;
        const float* src; int K, Kp, off;
        if (idx < W_Q)        { src = kv_w;   K = 180; Kp = KP;  off = idx - W_KV; }
        else if (idx < W_PROJ){ src = q_w;    K = 180; Kp = KP;  off = idx - W_Q; }
        else if (idx < W_FC1) { src = proj_w; K = 180; Kp = KP;  off = idx - W_PROJ; }
        else if (idx < W_FC2) { src = fc1_w;  K = 180; Kp = KP;  off = idx - W_FC1; }
        else                  { src = fc2_w;  K = 720; Kp = 720; off = idx - W_FC2; }
        int n = off / Kp, kk = off - n * Kp;
        w16[idx] = (kk < K) ? __float2half(src[n * K + kk]) : __float2half(0.f);
    }
}

// ---------------- standalone LN2 (half in stride C_DIM, half out stride KP) --
__global__ void __launch_bounds__(256) ln2_kernel(
    const __half* __restrict__ x, const float* __restrict__ g,
    const float* __restrict__ b, __half* __restrict__ out)
{
    int row = blockIdx.x * 8 + (threadIdx.x >> 5);
    ln_row_h(x + (size_t)row * C_DIM, g, b, out + (size_t)row * KP);
}

// ---------------- shared epilogue ---------------------------------------------
// EP: 0 none, 1 +res fp32, 2 exact GELU, 3 +res half. OH: write half.
template<int EP, int OH>
__device__ __forceinline__ void gemm_epilogue(
    float c[2][4][4], const float* __restrict__ bias,
    const float* __restrict__ res, const __half* __restrict__ resh,
    float* __restrict__ C, __half* __restrict__ Ch,
    int N, int bm, int bn, int wm, int wn, int gid, int tig)
{
    #pragma unroll
    for (int mi = 0; mi < 2; mi++) {
        int row = bm + wm + mi * 16 + gid;
        #pragma unroll
        for (int ni = 0; ni < 4; ni++) {
            int col = bn + wn + ni * 8 + tig * 2;
            if (col < N) {
                float v0 = c[mi][ni][0] + bias[col];
                float v1 = c[mi][ni][1] + bias[col + 1];
                float v2 = c[mi][ni][2] + bias[col];
                float v3 = c[mi][ni][3] + bias[col + 1];
                if (EP == 1) {
                    v0 += res[(size_t)row * N + col];
                    v1 += res[(size_t)row * N + col + 1];
                    v2 += res[(size_t)(row + 8) * N + col];
                    v3 += res[(size_t)(row + 8) * N + col + 1];
                }
                if (EP == 3) {
                    float2 r0 = __half22float2(*(const __half2*)(resh + (size_t)row * N + col));
                    float2 r1 = __half22float2(*(const __half2*)(resh + (size_t)(row + 8) * N + col));
                    v0 += r0.x; v1 += r0.y; v2 += r1.x; v3 += r1.y;
                }
                if (EP == 2) {
                    v0 = 0.5f * v0 * (1.f + erff(v0 * 0.70710678118654752f));
                    v1 = 0.5f * v1 * (1.f + erff(v1 * 0.70710678118654752f));
                    v2 = 0.5f * v2 * (1.f + erff(v2 * 0.70710678118654752f));
                    v3 = 0.5f * v3 * (1.f + erff(v3 * 0.70710678118654752f));
                }
                if (OH) {
                    *(__half2*)(Ch + (size_t)row * N + col)       = __floats2half2_rn(v0, v1);
                    *(__half2*)(Ch + (size_t)(row + 8) * N + col) = __floats2half2_rn(v2, v3);
                } else {
                    *(float2*)(C + (size_t)row * N + col)       = make_float2(v0, v1);
                    *(float2*)(C + (size_t)(row + 8) * N + col) = make_float2(v2, v3);
                }
            }
        }
    }
}

// ---------------- single-shot fp16 GEMM (Kp = 192, BM=64, 128 threads) --------
// Full tiles staged once; one sync; 96 HMMA/warp with register-double-buffered
// ldmatrix prefetch. 51.2 KB smem -> 4 blocks/SM for staging overlap.
template<int EP, int OH>
__device__ __forceinline__ void gemm_body_full(
    const __half* __restrict__ A, const __half* __restrict__ W,
    const float* __restrict__ bias, const float* __restrict__ res,
    const __half* __restrict__ resh,
    float* __restrict__ C, __half* __restrict__ Ch,
    int N, int bm, int bn, __half* sm)
{
    __half* As = sm;
    __half* Ws = sm + 64 * GSTR2;

    const int t    = threadIdx.x;       // 0..127
    const int warp = t >> 5;            // 0..3
    const int lane = t & 31;
    const int wm   = (warp >> 1) * 32;  // 0,32
    const int wn   = (warp & 1) * 32;   // 0,32
    const int gid  = lane >> 2;
    const int tig  = lane & 3;

    const int l8  = lane & 7;
    const int b3  = (lane >> 3) & 1;
    const int b4  = (lane >> 4) & 1;
    const int a_row  = wm + l8 + b3 * 8;
    const int a_koff = b4 * 8;
    const int b_rowp = wn + b4 * 8 + l8;
    const int b_koff = b3 * 8;

    // stage A: 64 rows x 24 c8 = 1536 chunks; W: 64 x 24 = 1536 (128 threads)
    #pragma unroll
    for (int i = 0; i < 12; i++) {
        int idx = t + i * 128;
        int r = idx / 24, c8 = idx - r * 24;
        cp_async16h(&As[r * GSTR2 + c8 * 8],
                    A + (size_t)(bm + r) * KP + c8 * 8, true);
    }
    #pragma unroll
    for (int i = 0; i < 12; i++) {
        int idx = t + i * 128;
        int r = idx / 24, c8 = idx - r * 24;
        int n = bn + r;
        bool ok = (n < N);
        const __half* src = W + (size_t)(ok ? n : 0) * KP + c8 * 8;
        cp_async16h(&Ws[r * GSTR2 + c8 * 8], src, ok);
    }
    cp_commit();

    float c[2][4][4];
    #pragma unroll
    for (int mi = 0; mi < 2; mi++)
        #pragma unroll
        for (int ni = 0; ni < 4; ni++)
            #pragma unroll
            for (int u = 0; u < 4; u++) c[mi][ni][u] = 0.f;

    cp_wait<0>();
    __syncthreads();

    const uint32_t As_u = smem_u32(As);
    const uint32_t Ws_u = smem_u32(Ws);

    uint32_t af[2][2][4], bf[2][4][2];
    auto ldfrag = [&](int k16, int buf) {
        const int kk = k16 * 16;
        #pragma unroll
        for (int mi = 0; mi < 2; mi++)
            ldsm_x4(af[buf][mi], As_u + 2 * ((a_row + mi * 16) * GSTR2 + kk + a_koff));
        #pragma unroll
        for (int p = 0; p < 2; p++) {
            uint32_t r[4];
            ldsm_x4(r, Ws_u + 2 * ((b_rowp + p * 16) * GSTR2 + kk + b_koff));
            bf[buf][2 * p][0] = r[0]; bf[buf][2 * p][1] = r[1];
            bf[buf][2 * p + 1][0] = r[2]; bf[buf][2 * p + 1][1] = r[3];
        }
    };

    ldfrag(0, 0);
    #pragma unroll
    for (int k16 = 0; k16 < 12; k16++) {
        if (k16 + 1 < 12) ldfrag(k16 + 1, (k16 + 1) & 1);
        const int buf = k16 & 1;
        #pragma unroll
        for (int mi = 0; mi < 2; mi++)
            #pragma unroll
            for (int ni = 0; ni < 4; ni++)
                mma_f16(c[mi][ni], af[buf][mi], bf[buf][ni]);
    }

    gemm_epilogue<EP, OH>(c, bias, res, resh, C, Ch, N, bm, bn, wm, wn, gid, tig);
}

template<int EP, int OH>
__global__ void __launch_bounds__(128, 4) gemm_full(
    const __half* __restrict__ A, const __half* __restrict__ W,
    const float* __restrict__ bias, const float* __restrict__ res,
    float* __restrict__ C, __half* __restrict__ Ch, int N)
{
    extern __shared__ __half smh[];
    gemm_body_full<EP, OH>(A, W, bias, res, nullptr, C, Ch, N,
                           blockIdx.y * 64, blockIdx.x * 64, smh);
}

// merged kv + q projection -> HALF outputs (single-shot, BM=64)
__global__ void __launch_bounds__(128, 4) qkv_gemm(
    const __half* __restrict__ xn, const __half* __restrict__ yn,
    const __half* __restrict__ w16,
    const float* __restrict__ kv_b, const float* __restrict__ q_b,
    __half* __restrict__ kvh, __half* __restrict__ qh)
{
    extern __shared__ __half smh[];
    if (blockIdx.x < 6)
        gemm_body_full<0, 1>(xn, w16 + W_KV, kv_b, nullptr, nullptr, nullptr, kvh,
                             2 * C_DIM, blockIdx.y * 64, blockIdx.x * 64, smh);
    else
        gemm_body_full<0, 1>(yn, w16 + W_Q, q_b, nullptr, nullptr, nullptr, qh,
                             C_DIM, blockIdx.y * 64, (blockIdx.x - 6) * 64, smh);
}

// ---------------- looped fp16 GEMM (for fc2: Kp = 720) ------------------------
template<int EP, int OH>
__global__ void __launch_bounds__(256, 4) gemm_loop(
    const __half* __restrict__ A, const __half* __restrict__ W,
    const float* __restrict__ bias, const __half* __restrict__ resh,
    float* __restrict__ C, __half* __restrict__ Ch, int N, int Kp)
{
    extern __shared__ __half smh[];
    __half* Ab[2] = { smh, smh + ABUF_H };
    __half* Wb[2] = { smh + 2 * ABUF_H, smh + 2 * ABUF_H + WBUF_H };

    const int t    = threadIdx.x;
    const int warp = t >> 5;
    const int lane = t & 31;
    const int wm   = (warp >> 1) * 32;
    const int wn   = (warp & 1) * 32;
    const int gid  = lane >> 2;
    const int tig  = lane & 3;
    const int bm   = blockIdx.y * 128;
    const int bn   = blockIdx.x * 64;
    const int nk   = Kp / 48;

    const int l8  = lane & 7;
    const int b3  = (lane >> 3) & 1;
    const int b4  = (lane >> 4) & 1;
    const int a_row  = wm + l8 + b3 * 8;
    const int a_koff = b4 * 8;
    const int b_rowp = wn + b4 * 8 + l8;
    const int b_koff = b3 * 8;

    auto stage = [&](int k0, int bufi) {
        __half* a = Ab[bufi];
        __half* w = Wb[bufi];
        #pragma unroll
        for (int i = 0; i < 3; i++) {
            int idx = t + i * 256;
            int r = idx / 6, c8 = idx - r * 6;
            cp_async16h(&a[r * HSTRIDE + c8 * 8],
                        A + (size_t)(bm + r) * Kp + k0 + c8 * 8, true);
        }
        #pragma unroll
        for (int i = 0; i < 2; i++) {
            int idx = t + i * 256;
            if (idx < 384) {
                int r = idx / 6, c8 = idx - r * 6;
                int n = bn + r;
                bool ok = (n < N);
                const __half* src = W + (size_t)(ok ? n : 0) * Kp + k0 + c8 * 8;
                cp_async16h(&w[r * HSTRIDE + c8 * 8], src, ok);
            }
        }
    };

    float c[2][4][4];
    #pragma unroll
    for (int mi = 0; mi < 2; mi++)
        #pragma unroll
        for (int ni = 0; ni < 4; ni++)
            #pragma unroll
            for (int u = 0; u < 4; u++) c[mi][ni][u] = 0.f;

    stage(0, 0);
    cp_commit();

    for (int i = 0; i < nk; i++) {
        if (i + 1 < nk) {
            stage((i + 1) * 48, (i + 1) & 1);
            cp_commit();
            cp_wait<1>();
        } else {
            cp_wait<0>();
        }
        __syncthreads();

        const uint32_t As = smem_u32(Ab[i & 1]);
        const uint32_t Ws = smem_u32(Wb[i & 1]);
        #pragma unroll
        for (int k16 = 0; k16 < 3; k16++) {
            const int kk = k16 * 16;
            uint32_t a[2][4], b[4][2];
            #pragma unroll
            for (int mi = 0; mi < 2; mi++)
                ldsm_x4(a[mi], As + 2 * ((a_row + mi * 16) * HSTRIDE + kk + a_koff));
            #pragma unroll
            for (int p = 0; p < 2; p++) {
                uint32_t r[4];
                ldsm_x4(r, Ws + 2 * ((b_rowp + p * 16) * HSTRIDE + kk + b_koff));
                b[2 * p][0] = r[0]; b[2 * p][1] = r[1];
                b[2 * p + 1][0] = r[2]; b[2 * p + 1][1] = r[3];
            }
            #pragma unroll
            for (int mi = 0; mi < 2; mi++)
                #pragma unroll
                for (int ni = 0; ni < 4; ni++)
                    mma_f16(c[mi][ni], a[mi], b[ni]);
        }
        __syncthreads();
    }

    gemm_epilogue<EP, OH>(c, bias, nullptr, resh, C, Ch, N, bm, bn, wm, wn, gid, tig);
}

// ---------------- fp16 tensor-core window attention ---------------------------
__global__ void __launch_bounds__(256, 2) attn_tc(
    const __half* __restrict__ qh, const __half* __restrict__ kvh,
    const float* __restrict__ biasF, __half* __restrict__ out)
{
    __shared__ __half ks [KC * KSTR];   // [key][d]
    __shared__ __half vsT[32 * VSTR];   // [d][key]

    const int wi   = blockIdx.x;      // 0..63 : b*16 + wy*4 + wx
    const int head = blockIdx.y;
    const int b  = wi >> 4;
    const int wy = (wi >> 2) & 3;
    const int wx = wi & 3;
    const int t    = threadIdx.x;
    const int warp = t >> 5;
    const int lane = t & 31;
    const int gid  = lane >> 2;
    const int tig  = lane & 3;
    const int wq   = warp * 32;

    const int l8 = lane & 7;
    const int b3 = (lane >> 3) & 1;
    const int b4 = (lane >> 4) & 1;

    // ---- load Q fragments once (scaled, fp16, d padded to 32) ----
    uint32_t qf[2][2][4];
    #pragma unroll
    for (int mi = 0; mi < 2; mi++) {
        int iy = (wq + mi * 16) >> 4;
        int gy = wy * WS + iy;
        const __half* q0 = qh + ((size_t)(b * 4096 + gy * 64 + wx * WS + gid)) * C_DIM + head * DHEAD;
        const __half* q1 = qh + ((size_t)(b * 4096 + gy * 64 + wx * WS + gid + 8)) * C_DIM + head * DHEAD;
        const float sc = 0.18257418583505537f;  // 30^-0.5
        #pragma unroll
        for (int kd = 0; kd < 2; kd++) {
            int d0 = kd * 16 + 2 * tig;
            int d2 = d0 + 8;
            float2 f0 = __half22float2(*(const __half2*)(q0 + d0));
            float2 f1 = __half22float2(*(const __half2*)(q1 + d0));
            float2 f2 = (d2 < DHEAD) ? __half22float2(*(const __half2*)(q0 + d2))
                                     : make_float2(0.f, 0.f);
            float2 f3 = (d2 < DHEAD) ? __half22float2(*(const __half2*)(q1 + d2))
                                     : make_float2(0.f, 0.f);
            qf[mi][kd][0] = pack_h2(f0.x * sc, f0.y * sc);
            qf[mi][kd][1] = pack_h2(f1.x * sc, f1.y * sc);
            qf[mi][kd][2] = pack_h2(f2.x * sc, f2.y * sc);
            qf[mi][kd][3] = pack_h2(f3.x * sc, f3.y * sc);
        }
    }

    const float* bfh = biasF + (size_t)head * (72 * 16 * 128);
    const uint32_t ks_u  = smem_u32(ks);
    const uint32_t vsT_u = smem_u32(vsT);

    float l[2][2] = {{0.f, 0.f}, {0.f, 0.f}};
    float o[2][4][4];
    #pragma unroll
    for (int mi = 0; mi < 2; mi++)
        #pragma unroll
        for (int nj = 0; nj < 4; nj++)
            #pragma unroll
            for (int u = 0; u < 4; u++) o[mi][nj][u] = 0.f;

    for (int c0 = 0; c0 < NKEY; c0 += KC) {
        __syncthreads();
        for (int idx = t; idx < KC * 16; idx += 256) {
            int j  = idx >> 4;
            int d2 = idx & 15;
            int key = c0 + j;
            int jy = key / OWS;
            int jx = key - jy * OWS;
            int ky = wy * WS - 4 + jy;
            int kx = wx * WS - 4 + jx;
            __half2 kval = __floats2half2_rn(0.f, 0.f), vval = kval;
            if (d2 < 15 && (unsigned)ky < 64u && (unsigned)kx < 64u) {
                const __half* p = kvh + ((size_t)(b * 4096 + ky * 64 + kx)) * (2 * C_DIM)
                                      + head * DHEAD + 2 * d2;
                kval = *(const __half2*)p;
                vval = *(const __half2*)(p + C_DIM);
            }
            *(__half2*)&ks[j * KSTR + 2 * d2] = kval;
            vsT[(2 * d2) * VSTR + j]     = __low2half(vval);
            vsT[(2 * d2 + 1) * VSTR + j] = __high2half(vval);
        }
        __syncthreads();

        float la[2][2] = {{0.f, 0.f}, {0.f, 0.f}};

        #pragma unroll
        for (int u = 0; u < 4; u++) {
            float se[2][4], so[2][4];
            #pragma unroll
            for (int mi = 0; mi < 2; mi++)
                #pragma unroll
                for (int w = 0; w < 4; w++) { se[mi][w] = 0.f; so[mi][w] = 0.f; }

            #pragma unroll
            for (int kd = 0; kd < 2; kd++) {
                int keyrow = u * 16 + b4 * 8 + l8;
                int doff   = kd * 16 + b3 * 8;
                uint32_t r[4];
                ldsm_x4(r, ks_u + 2 * (keyrow * KSTR + doff));
                uint32_t be[2] = { r[0], r[1] };
                uint32_t bo[2] = { r[2], r[3] };
                #pragma unroll
                for (int mi = 0; mi < 2; mi++) {
                    mma_f16(se[mi], qf[mi][kd], be);
                    mma_f16(so[mi], qf[mi][kd], bo);
                }
            }

            int k8 = (c0 >> 3) + 2 * u;
            #pragma unroll
            for (int mi = 0; mi < 2; mi++) {
                int qblk = warp * 2 + mi;
                float4 bve = *(const float4*)(bfh + (((size_t)k8 * 16 + qblk) << 7) + (lane << 2));
                float4 bvo = *(const float4*)(bfh + (((size_t)(k8 + 1) * 16 + qblk) << 7) + (lane << 2));
                se[mi][0] = __expf(se[mi][0] + bve.x);
                se[mi][1] = __expf(se[mi][1] + bve.y);
                se[mi][2] = __expf(se[mi][2] + bve.z);
                se[mi][3] = __expf(se[mi][3] + bve.w);
                so[mi][0] = __expf(so[mi][0] + bvo.x);
                so[mi][1] = __expf(so[mi][1] + bvo.y);
                so[mi][2] = __expf(so[mi][2] + bvo.z);
                so[mi][3] = __expf(so[mi][3] + bvo.w);
                la[mi][0] += se[mi][0] + se[mi][1] + so[mi][0] + so[mi][1];
                la[mi][1] += se[mi][2] + se[mi][3] + so[mi][2] + so[mi][3];
            }

            uint32_t ap[2][4];
            #pragma unroll
            for (int mi = 0; mi < 2; mi++) {
                ap[mi][0] = pack_h2(se[mi][0], se[mi][1]);
                ap[mi][1] = pack_h2(se[mi][2], se[mi][3]);
                ap[mi][2] = pack_h2(so[mi][0], so[mi][1]);
                ap[mi][3] = pack_h2(so[mi][2], so[mi][3]);
            }

            uint32_t bvv[4][2];
            #pragma unroll
            for (int p = 0; p < 2; p++) {
                int drow   = (2 * p + b4) * 8 + l8;
                int keyoff = u * 16 + b3 * 8;
                uint32_t r[4];
                ldsm_x4(r, vsT_u + 2 * (drow * VSTR + keyoff));
                bvv[2 * p][0] = r[0]; bvv[2 * p][1] = r[1];
                bvv[2 * p + 1][0] = r[2]; bvv[2 * p + 1][1] = r[3];
            }
            #pragma unroll
            for (int nj = 0; nj < 4; nj++)
                #pragma unroll
                for (int mi = 0; mi < 2; mi++)
                    mma_f16(o[mi][nj], ap[mi], bvv[nj]);
        }

        #pragma unroll
        for (int mi = 0; mi < 2; mi++) {
            float la0 = la[mi][0], la1 = la[mi][1];
            la0 += __shfl_xor_sync(0xffffffffu, la0, 1);
            la0 += __shfl_xor_sync(0xffffffffu, la0, 2);
            la1 += __shfl_xor_sync(0xffffffffu, la1, 1);
            la1 += __shfl_xor_sync(0xffffffffu, la1, 2);
            l[mi][0] += la0; l[mi][1] += la1;
        }
    }

    #pragma unroll
    for (int mi = 0; mi < 2; mi++) {
        float inv0 = 1.f / l[mi][0];
        float inv1 = 1.f / l[mi][1];
        int iy = (wq + mi * 16) >> 4;
        int gy = wy * WS + iy;
        __half* o0 = out + ((size_t)(b * 4096 + gy * 64 + wx * WS + gid)) * KP + head * DHEAD;
        __half* o1 = out + ((size_t)(b * 4096 + gy * 64 + wx * WS + gid + 8)) * KP + head * DHEAD;
        #pragma unroll
        for (int nj = 0; nj < 4; nj++) {
            int d = nj * 8 + 2 * tig;
            if (d < DHEAD) {
                *(__half2*)(o0 + d) = __floats2half2_rn(o[mi][nj][0] * inv0, o[mi][nj][1] * inv0);
                *(__half2*)(o1 + d) = __floats2half2_rn(o[mi][nj][2] * inv1, o[mi][nj][3] * inv1);
            }
        }
    }
    if (head == 0) {
        int pix = b * 4096 + (wy * WS + (t >> 4)) * 64 + wx * WS + (t & 15);
        __half* pr = out + (size_t)pix * KP + C_DIM;
        __half2 z = __floats2half2_rn(0.f, 0.f);
        #pragma unroll
        for (int cc = 0; cc < 6; cc++) *(__half2*)(pr + 2 * cc) = z;
    }
}

// ---------------- launch --------------------------------------------------
extern "C" void kernel_launch(void* const* d_in, const int* in_sizes, int n_in,
                              void* d_out, int out_size)
{
    const float* x      = (const float*)d_in[0];
    const float* y      = (const float*)d_in[1];
    const float* n1g    = (const float*)d_in[2];
    const float* n1b    = (const float*)d_in[3];
    const float* kv_w   = (const float*)d_in[4];
    const float* kv_b   = (const float*)d_in[5];
    const float* q_w    = (const float*)d_in[6];
    const float* q_b    = (const float*)d_in[7];
    const float* rpb    = (const float*)d_in[8];
    const float* proj_w = (const float*)d_in[9];
    const float* proj_b = (const float*)d_in[10];
    const float* n2g    = (const float*)d_in[11];
    const float* n2b    = (const float*)d_in[12];
    const float* fc1_w  = (const float*)d_in[13];
    const float* fc1_b  = (const float*)d_in[14];
    const float* fc2_w  = (const float*)d_in[15];
    const float* fc2_b  = (const float*)d_in[16];
    const int*   rpi    = (const int*)d_in[17];
    float* outp = (float*)d_out;

    __half *xn, *yn, *ath, *xn2, *h1, *w16, *kvh, *qh, *xoh;
    float *biasp;
    cudaGetSymbolAddress((void**)&xn,    g_xn_h);
    cudaGetSymbolAddress((void**)&yn,    g_yn_h);
    cudaGetSymbolAddress((void**)&ath,   g_at_h);
    cudaGetSymbolAddress((void**)&xn2,   g_xn2_h);
    cudaGetSymbolAddress((void**)&h1,    g_h1_h);
    cudaGetSymbolAddress((void**)&w16,   g_w16);
    cudaGetSymbolAddress((void**)&kvh,   g_kv_h);
    cudaGetSymbolAddress((void**)&qh,    g_q_h);
    cudaGetSymbolAddress((void**)&xoh,   g_xo_h);
    cudaGetSymbolAddress((void**)&biasp, g_bias);

    const int loop_smem = (2 * ABUF_H + 2 * WBUF_H) * 2;   // 43008 bytes
    cudaFuncSetAttribute(qkv_gemm,        cudaFuncAttributeMaxDynamicSharedMemorySize, FULL_SMEM);
    cudaFuncSetAttribute(gemm_full<1,1>,  cudaFuncAttributeMaxDynamicSharedMemorySize, FULL_SMEM);
    cudaFuncSetAttribute(gemm_full<2,1>,  cudaFuncAttributeMaxDynamicSharedMemorySize, FULL_SMEM);
    cudaFuncSetAttribute(gemm_loop<3,0>,  cudaFuncAttributeMaxDynamicSharedMemorySize, loop_smem);

    // fused prologue: LN(x), LN(y), bias table, weight conversion
    prep_kernel<<<PREP_BLKS, 256>>>(x, y, n1g, n1b, xn, yn,
                                    rpi, rpb, biasp,
                                    kv_w, q_w, proj_w, fc1_w, fc2_w, w16);

    // kv + q projections (single-shot fp16 GEMM, BM=64 -> half outputs)
    qkv_gemm<<<dim3(9, M_ROWS / 64), 128, FULL_SMEM>>>(xn, yn, w16, kv_b, q_b, kvh, qh);

    // windowed attention (fp16 mma + ldmatrix, half output)
    attn_tc<<<dim3(64, NHEAD), 256>>>(qh, kvh, biasp, ath);

    // xo = attn @ proj_w^T + proj_b + x   (HALF out)
    gemm_full<1,1><<<dim3(3, M_ROWS / 64), 128, FULL_SMEM>>>(ath, w16 + W_PROJ, proj_b, x,
                                                             nullptr, xoh, C_DIM);

    // LN2 (half in -> half out)
    ln2_kernel<<<M_ROWS / 8, 256>>>(xoh, n2g, n2b, xn2);

    // h1 = gelu(xn2 @ fc1_w^T + fc1_b)  (half out)
    gemm_full<2,1><<<dim3(12, M_ROWS / 64), 128, FULL_SMEM>>>(xn2, w16 + W_FC1, fc1_b, nullptr,
                                                              nullptr, h1, 4 * C_DIM);

    // out = h1 @ fc2_w^T + fc2_b + xo(half)  (fp32 out, looped K=720)
    gemm_loop<3,0><<<dim3(3, M_ROWS / 128), 256, loop_smem>>>(h1, w16 + W_FC2, fc2_b, xoh,
                                                              outp, nullptr, C_DIM, 720);
}

// round 16
// speedup vs baseline: 1.0229x; 1.0229x over previous
#include <cuda_runtime.h>
#include <cuda_fp16.h>
#include <math.h>
#include <stdint.h>

// Problem constants
#define M_ROWS 16384            // b * h * w = 4*64*64
#define C_DIM  180
#define KP     192              // padded K for fp16 GEMM operands (12*16)
#define NHEAD  6
#define DHEAD  30
#define WS     16
#define OWS    24
#define NKEY   (OWS*OWS)        // 576
#define NQ     (WS*WS)          // 256
#define KC     64               // keys per attention chunk

#define HSTRIDE 56              // looped-GEMM smem row stride (halves)
#define GSTR2   200             // single-shot GEMM smem row stride (halves)
#define KSTR    40              // attention K smem stride (halves)
#define VSTR    72              // attention V^T smem stride (halves)
#define ABUF_H (128 * HSTRIDE)
#define WBUF_H (64 * HSTRIDE)
#define FULL_SMEM ((128 * GSTR2 + 64 * GSTR2) * 2)   // 76800 bytes (BM=128)

// weight16 segment offsets (halves)
#define W_KV   0
#define W_Q    (W_KV + 360 * KP)
#define W_PROJ (W_Q + 180 * KP)
#define W_FC1  (W_PROJ + 180 * KP)
#define W_FC2  (W_FC1 + 720 * KP)
#define W_TOT  (W_FC2 + 180 * 720)

// prep kernel block ranges
#define LN_BLKS   (M_ROWS / 8)                         // 2048 per tensor
#define BIAS_BLKS ((NHEAD * NKEY * NQ + 255) / 256)    // 3456
#define CONV_BLKS ((W_TOT + 255) / 256)                // 1587
#define PREP_BLKS (2 * LN_BLKS + BIAS_BLKS + CONV_BLKS)

// ---------------- scratch (device globals; no allocation allowed) -----------
__device__ __half g_xn_h [M_ROWS * KP];
__device__ __half g_yn_h [M_ROWS * KP];
__device__ __half g_at_h [M_ROWS * KP];
__device__ __half g_xn2_h[M_ROWS * KP];
__device__ __half g_h1_h [M_ROWS * 4 * C_DIM];
__device__ __half g_w16  [W_TOT];
__device__ __half g_kv_h [M_ROWS * 2 * C_DIM];
__device__ __half g_q_h  [M_ROWS * C_DIM];
__device__ __half g_xo_h [M_ROWS * C_DIM];
// bias in C-fragment order: [h][k8 (72)][q16 (16)][lane (32)][4]
__device__ float  g_bias [NHEAD * NKEY * NQ];

// ---------------- mma / ldmatrix / async helpers ------------------------------
__device__ __forceinline__ void mma_f16(float c[4], const uint32_t a[4], const uint32_t b[2]) {
    asm volatile(
        "mma.sync.aligned.m16n8k16.row.col.f32.f16.f16.f32 "
        "{%0,%1,%2,%3},{%4,%5,%6,%7},{%8,%9},{%0,%1,%2,%3};"
        : "+f"(c[0]), "+f"(c[1]), "+f"(c[2]), "+f"(c[3])
        : "r"(a[0]), "r"(a[1]), "r"(a[2]), "r"(a[3]), "r"(b[0]), "r"(b[1]));
}

__device__ __forceinline__ void ldsm_x4(uint32_t r[4], uint32_t addr) {
    asm volatile("ldmatrix.sync.aligned.m8n8.x4.shared.b16 {%0,%1,%2,%3}, [%4];"
                 : "=r"(r[0]), "=r"(r[1]), "=r"(r[2]), "=r"(r[3]) : "r"(addr));
}

__device__ __forceinline__ uint32_t smem_u32(const void* p) {
    return (uint32_t)__cvta_generic_to_shared(p);
}

__device__ __forceinline__ void cp_async16h(__half* smem_dst, const __half* gmem_src, bool pred) {
    uint32_t s = smem_u32(smem_dst);
    int sz = pred ? 16 : 0;
    asm volatile("cp.async.cg.shared.global [%0], [%1], 16, %2;"
                 :: "r"(s), "l"(gmem_src), "r"(sz));
}
__device__ __forceinline__ void cp_commit() {
    asm volatile("cp.async.commit_group;");
}
template<int N>
__device__ __forceinline__ void cp_wait() {
    asm volatile("cp.async.wait_group %0;" :: "n"(N));
}

__device__ __forceinline__ uint32_t pack_h2(float lo, float hi) {
    __half2 h = __floats2half2_rn(lo, hi);
    return *(uint32_t*)&h;
}

// ---------------- LayerNorm row bodies ----------------------------------------
__device__ __forceinline__ void ln_row(
    const float* __restrict__ xr, const float* __restrict__ g,
    const float* __restrict__ b, __half* __restrict__ orow)
{
    int lane = threadIdx.x & 31;
    float v[6];
    float s = 0.f;
    #pragma unroll
    for (int i = 0; i < 6; i++) {
        int idx = lane + 32 * i;
        v[i] = (idx < C_DIM) ? xr[idx] : 0.f;
        s += v[i];
    }
    #pragma unroll
    for (int o = 16; o > 0; o >>= 1) s += __shfl_xor_sync(0xffffffffu, s, o);
    float mean = s * (1.f / C_DIM);
    float s2 = 0.f;
    #pragma unroll
    for (int i = 0; i < 6; i++) {
        int idx = lane + 32 * i;
        float d = (idx < C_DIM) ? (v[i] - mean) : 0.f;
        s2 += d * d;
    }
    #pragma unroll
    for (int o = 16; o > 0; o >>= 1) s2 += __shfl_xor_sync(0xffffffffu, s2, o);
    float r = rsqrtf(s2 * (1.f / C_DIM) + 1e-5f);
    #pragma unroll
    for (int i = 0; i < 6; i++) {
        int idx = lane + 32 * i;
        float res = (idx < C_DIM) ? (v[i] - mean) * r * g[idx] + b[idx] : 0.f;
        orow[idx] = __float2half(res);
    }
}

__device__ __forceinline__ void ln_row_h(
    const __half* __restrict__ xr, const float* __restrict__ g,
    const float* __restrict__ b, __half* __restrict__ orow)
{
    int lane = threadIdx.x & 31;
    float v[6];
    float s = 0.f;
    #pragma unroll
    for (int i = 0; i < 6; i++) {
        int idx = lane + 32 * i;
        v[i] = (idx < C_DIM) ? __half2float(xr[idx]) : 0.f;
        s += v[i];
    }
    #pragma unroll
    for (int o = 16; o > 0; o >>= 1) s += __shfl_xor_sync(0xffffffffu, s, o);
    float mean = s * (1.f / C_DIM);
    float s2 = 0.f;
    #pragma unroll
    for (int i = 0; i < 6; i++) {
        int idx = lane + 32 * i;
        float d = (idx < C_DIM) ? (v[i] - mean) : 0.f;
        s2 += d * d;
    }
    #pragma unroll
    for (int o = 16; o > 0; o >>= 1) s2 += __shfl_xor_sync(0xffffffffu, s2, o);
    float r = rsqrtf(s2 * (1.f / C_DIM) + 1e-5f);
    #pragma unroll
    for (int i = 0; i < 6; i++) {
        int idx = lane + 32 * i;
        float res = (idx < C_DIM) ? (v[i] - mean) * r * g[idx] + b[idx] : 0.f;
        orow[idx] = __float2half(res);
    }
}

// ---------------- fused prologue: LN(x), LN(y), bias table, weight conv ------
__global__ void __launch_bounds__(256) prep_kernel(
    const float* __restrict__ x, const float* __restrict__ y,
    const float* __restrict__ n1g, const float* __restrict__ n1b,
    __half* __restrict__ xn, __half* __restrict__ yn,
    const int* __restrict__ rpi, const float* __restrict__ rpb,
    float* __restrict__ biasF,
    const float* __restrict__ kv_w, const float* __restrict__ q_w,
    const float* __restrict__ proj_w, const float* __restrict__ fc1_w,
    const float* __restrict__ fc2_w, __half* __restrict__ w16)
{
    int blk = blockIdx.x;
    if (blk < 2 * LN_BLKS) {
        const float* src = (blk < LN_BLKS) ? x : y;
        __half* dst      = (blk < LN_BLKS) ? xn : yn;
        int base = (blk < LN_BLKS) ? blk : blk - LN_BLKS;
        int row = base * 8 + (threadIdx.x >> 5);
        ln_row(src + (size_t)row * C_DIM, n1g, n1b, dst + (size_t)row * KP);
        return;
    }
    blk -= 2 * LN_BLKS;
    if (blk < BIAS_BLKS) {
        int idx = blk * 256 + threadIdx.x;
        if (idx >= NHEAD * NKEY * NQ) return;
        int u    = idx & 3;
        int lane = (idx >> 2) & 31;
        int qblk = (idx >> 7) & 15;
        int rest = idx >> 11;          // h*72 + k8
        int k8   = rest % 72;
        int h    = rest / 72;
        int gid = lane >> 2, tig = lane & 3;
        int qq = qblk * 16 + gid + ((u & 2) ? 8 : 0);
        int kk = k8 * 8 + 2 * tig + (u & 1);
        biasF[idx] = rpb[rpi[qq * NKEY + kk] * NHEAD + h];
        return;
    }
    blk -= BIAS_BLKS;
    {
        int idx = blk * 256 + threadIdx.x;
        if (idx >= W_TOT) return;
        const float* src; int K, Kp, off;
        if (idx < W_Q)        { src = kv_w;   K = 180; Kp = KP;  off = idx - W_KV; }
        else if (idx < W_PROJ){ src = q_w;    K = 180; Kp = KP;  off = idx - W_Q; }
        else if (idx < W_FC1) { src = proj_w; K = 180; Kp = KP;  off = idx - W_PROJ; }
        else if (idx < W_FC2) { src = fc1_w;  K = 180; Kp = KP;  off = idx - W_FC1; }
        else                  { src = fc2_w;  K = 720; Kp = 720; off = idx - W_FC2; }
        int n = off / Kp, kk = off - n * Kp;
        w16[idx] = (kk < K) ? __float2half(src[n * K + kk]) : __float2half(0.f);
    }
}

// ---------------- standalone LN2 (half in stride C_DIM, half out stride KP) --
__global__ void __launch_bounds__(256) ln2_kernel(
    const __half* __restrict__ x, const float* __restrict__ g,
    const float* __restrict__ b, __half* __restrict__ out)
{
    int row = blockIdx.x * 8 + (threadIdx.x >> 5);
    ln_row_h(x + (size_t)row * C_DIM, g, b, out + (size_t)row * KP);
}

// ---------------- shared epilogue ---------------------------------------------
// EP: 0 none, 1 +res fp32, 2 exact GELU, 3 +res half. OH: write half.
template<int EP, int OH>
__device__ __forceinline__ void gemm_epilogue(
    float c[2][4][4], const float* __restrict__ bias,
    const float* __restrict__ res, const __half* __restrict__ resh,
    float* __restrict__ C, __half* __restrict__ Ch,
    int N, int bm, int bn, int wm, int wn, int gid, int tig)
{
    #pragma unroll
    for (int mi = 0; mi < 2; mi++) {
        int row = bm + wm + mi * 16 + gid;
        #pragma unroll
        for (int ni = 0; ni < 4; ni++) {
            int col = bn + wn + ni * 8 + tig * 2;
            if (col < N) {
                float v0 = c[mi][ni][0] + bias[col];
                float v1 = c[mi][ni][1] + bias[col + 1];
                float v2 = c[mi][ni][2] + bias[col];
                float v3 = c[mi][ni][3] + bias[col + 1];
                if (EP == 1) {
                    v0 += res[(size_t)row * N + col];
                    v1 += res[(size_t)row * N + col + 1];
                    v2 += res[(size_t)(row + 8) * N + col];
                    v3 += res[(size_t)(row + 8) * N + col + 1];
                }
                if (EP == 3) {
                    float2 r0 = __half22float2(*(const __half2*)(resh + (size_t)row * N + col));
                    float2 r1 = __half22float2(*(const __half2*)(resh + (size_t)(row + 8) * N + col));
                    v0 += r0.x; v1 += r0.y; v2 += r1.x; v3 += r1.y;
                }
                if (EP == 2) {
                    v0 = 0.5f * v0 * (1.f + erff(v0 * 0.70710678118654752f));
                    v1 = 0.5f * v1 * (1.f + erff(v1 * 0.70710678118654752f));
                    v2 = 0.5f * v2 * (1.f + erff(v2 * 0.70710678118654752f));
                    v3 = 0.5f * v3 * (1.f + erff(v3 * 0.70710678118654752f));
                }
                if (OH) {
                    *(__half2*)(Ch + (size_t)row * N + col)       = __floats2half2_rn(v0, v1);
                    *(__half2*)(Ch + (size_t)(row + 8) * N + col) = __floats2half2_rn(v2, v3);
                } else {
                    *(float2*)(C + (size_t)row * N + col)       = make_float2(v0, v1);
                    *(float2*)(C + (size_t)(row + 8) * N + col) = make_float2(v2, v3);
                }
            }
        }
    }
}

// ---------------- single-shot fp16 GEMM (Kp = 192, BM=128, 256 threads) -------
// Full tiles staged once; one sync; 96 HMMA/warp with register-double-buffered
// ldmatrix prefetch (R14 configuration).
template<int EP, int OH>
__device__ __forceinline__ void gemm_body_full(
    const __half* __restrict__ A, const __half* __restrict__ W,
    const float* __restrict__ bias, const float* __restrict__ res,
    const __half* __restrict__ resh,
    float* __restrict__ C, __half* __restrict__ Ch,
    int N, int bm, int bn, __half* sm)
{
    __half* As = sm;
    __half* Ws = sm + 128 * GSTR2;

    const int t    = threadIdx.x;
    const int warp = t >> 5;
    const int lane = t & 31;
    const int wm   = (warp >> 1) * 32;
    const int wn   = (warp & 1) * 32;
    const int gid  = lane >> 2;
    const int tig  = lane & 3;

    const int l8  = lane & 7;
    const int b3  = (lane >> 3) & 1;
    const int b4  = (lane >> 4) & 1;
    const int a_row  = wm + l8 + b3 * 8;
    const int a_koff = b4 * 8;
    const int b_rowp = wn + b4 * 8 + l8;
    const int b_koff = b3 * 8;

    #pragma unroll
    for (int i = 0; i < 12; i++) {
        int idx = t + i * 256;
        int r = idx / 24, c8 = idx - r * 24;
        cp_async16h(&As[r * GSTR2 + c8 * 8],
                    A + (size_t)(bm + r) * KP + c8 * 8, true);
    }
    #pragma unroll
    for (int i = 0; i < 6; i++) {
        int idx = t + i * 256;
        int r = idx / 24, c8 = idx - r * 24;
        int n = bn + r;
        bool ok = (n < N);
        const __half* src = W + (size_t)(ok ? n : 0) * KP + c8 * 8;
        cp_async16h(&Ws[r * GSTR2 + c8 * 8], src, ok);
    }
    cp_commit();

    float c[2][4][4];
    #pragma unroll
    for (int mi = 0; mi < 2; mi++)
        #pragma unroll
        for (int ni = 0; ni < 4; ni++)
            #pragma unroll
            for (int u = 0; u < 4; u++) c[mi][ni][u] = 0.f;

    cp_wait<0>();
    __syncthreads();

    const uint32_t As_u = smem_u32(As);
    const uint32_t Ws_u = smem_u32(Ws);

    uint32_t af[2][2][4], bf[2][4][2];
    auto ldfrag = [&](int k16, int buf) {
        const int kk = k16 * 16;
        #pragma unroll
        for (int mi = 0; mi < 2; mi++)
            ldsm_x4(af[buf][mi], As_u + 2 * ((a_row + mi * 16) * GSTR2 + kk + a_koff));
        #pragma unroll
        for (int p = 0; p < 2; p++) {
            uint32_t r[4];
            ldsm_x4(r, Ws_u + 2 * ((b_rowp + p * 16) * GSTR2 + kk + b_koff));
            bf[buf][2 * p][0] = r[0]; bf[buf][2 * p][1] = r[1];
            bf[buf][2 * p + 1][0] = r[2]; bf[buf][2 * p + 1][1] = r[3];
        }
    };

    ldfrag(0, 0);
    #pragma unroll
    for (int k16 = 0; k16 < 12; k16++) {
        if (k16 + 1 < 12) ldfrag(k16 + 1, (k16 + 1) & 1);
        const int buf = k16 & 1;
        #pragma unroll
        for (int mi = 0; mi < 2; mi++)
            #pragma unroll
            for (int ni = 0; ni < 4; ni++)
                mma_f16(c[mi][ni], af[buf][mi], bf[buf][ni]);
    }

    gemm_epilogue<EP, OH>(c, bias, res, resh, C, Ch, N, bm, bn, wm, wn, gid, tig);
}

template<int EP, int OH>
__global__ void __launch_bounds__(256) gemm_full(
    const __half* __restrict__ A, const __half* __restrict__ W,
    const float* __restrict__ bias, const float* __restrict__ res,
    float* __restrict__ C, __half* __restrict__ Ch, int N)
{
    extern __shared__ __half smh[];
    gemm_body_full<EP, OH>(A, W, bias, res, nullptr, C, Ch, N,
                           blockIdx.y * 128, blockIdx.x * 64, smh);
}

// merged kv + q projection -> HALF outputs (single-shot, BM=128)
__global__ void __launch_bounds__(256) qkv_gemm(
    const __half* __restrict__ xn, const __half* __restrict__ yn,
    const __half* __restrict__ w16,
    const float* __restrict__ kv_b, const float* __restrict__ q_b,
    __half* __restrict__ kvh, __half* __restrict__ qh)
{
    extern __shared__ __half smh[];
    if (blockIdx.x < 6)
        gemm_body_full<0, 1>(xn, w16 + W_KV, kv_b, nullptr, nullptr, nullptr, kvh,
                             2 * C_DIM, blockIdx.y * 128, blockIdx.x * 64, smh);
    else
        gemm_body_full<0, 1>(yn, w16 + W_Q, q_b, nullptr, nullptr, nullptr, qh,
                             C_DIM, blockIdx.y * 128, (blockIdx.x - 6) * 64, smh);
}

// ---------------- looped fp16 GEMM (for fc2: Kp = 720) ------------------------
template<int EP, int OH>
__global__ void __launch_bounds__(256, 4) gemm_loop(
    const __half* __restrict__ A, const __half* __restrict__ W,
    const float* __restrict__ bias, const __half* __restrict__ resh,
    float* __restrict__ C, __half* __restrict__ Ch, int N, int Kp)
{
    extern __shared__ __half smh[];
    __half* Ab[2] = { smh, smh + ABUF_H };
    __half* Wb[2] = { smh + 2 * ABUF_H, smh + 2 * ABUF_H + WBUF_H };

    const int t    = threadIdx.x;
    const int warp = t >> 5;
    const int lane = t & 31;
    const int wm   = (warp >> 1) * 32;
    const int wn   = (warp & 1) * 32;
    const int gid  = lane >> 2;
    const int tig  = lane & 3;
    const int bm   = blockIdx.y * 128;
    const int bn   = blockIdx.x * 64;
    const int nk   = Kp / 48;

    const int l8  = lane & 7;
    const int b3  = (lane >> 3) & 1;
    const int b4  = (lane >> 4) & 1;
    const int a_row  = wm + l8 + b3 * 8;
    const int a_koff = b4 * 8;
    const int b_rowp = wn + b4 * 8 + l8;
    const int b_koff = b3 * 8;

    auto stage = [&](int k0, int bufi) {
        __half* a = Ab[bufi];
        __half* w = Wb[bufi];
        #pragma unroll
        for (int i = 0; i < 3; i++) {
            int idx = t + i * 256;
            int r = idx / 6, c8 = idx - r * 6;
            cp_async16h(&a[r * HSTRIDE + c8 * 8],
                        A + (size_t)(bm + r) * Kp + k0 + c8 * 8, true);
        }
        #pragma unroll
        for (int i = 0; i < 2; i++) {
            int idx = t + i * 256;
            if (idx < 384) {
                int r = idx / 6, c8 = idx - r * 6;
                int n = bn + r;
                bool ok = (n < N);
                const __half* src = W + (size_t)(ok ? n : 0) * Kp + k0 + c8 * 8;
                cp_async16h(&w[r * HSTRIDE + c8 * 8], src, ok);
            }
        }
    };

    float c[2][4][4];
    #pragma unroll
    for (int mi = 0; mi < 2; mi++)
        #pragma unroll
        for (int ni = 0; ni < 4; ni++)
            #pragma unroll
            for (int u = 0; u < 4; u++) c[mi][ni][u] = 0.f;

    stage(0, 0);
    cp_commit();

    for (int i = 0; i < nk; i++) {
        if (i + 1 < nk) {
            stage((i + 1) * 48, (i + 1) & 1);
            cp_commit();
            cp_wait<1>();
        } else {
            cp_wait<0>();
        }
        __syncthreads();

        const uint32_t As = smem_u32(Ab[i & 1]);
        const uint32_t Ws = smem_u32(Wb[i & 1]);
        #pragma unroll
        for (int k16 = 0; k16 < 3; k16++) {
            const int kk = k16 * 16;
            uint32_t a[2][4], b[4][2];
            #pragma unroll
            for (int mi = 0; mi < 2; mi++)
                ldsm_x4(a[mi], As + 2 * ((a_row + mi * 16) * HSTRIDE + kk + a_koff));
            #pragma unroll
            for (int p = 0; p < 2; p++) {
                uint32_t r[4];
                ldsm_x4(r, Ws + 2 * ((b_rowp + p * 16) * HSTRIDE + kk + b_koff));
                b[2 * p][0] = r[0]; b[2 * p][1] = r[1];
                b[2 * p + 1][0] = r[2]; b[2 * p + 1][1] = r[3];
            }
            #pragma unroll
            for (int mi = 0; mi < 2; mi++)
                #pragma unroll
                for (int ni = 0; ni < 4; ni++)
                    mma_f16(c[mi][ni], a[mi], b[ni]);
        }
        __syncthreads();
    }

    gemm_epilogue<EP, OH>(c, bias, nullptr, resh, C, Ch, N, bm, bn, wm, wn, gid, tig);
}

// ---------------- fp16 tensor-core window attention ---------------------------
__global__ void __launch_bounds__(256, 2) attn_tc(
    const __half* __restrict__ qh, const __half* __restrict__ kvh,
    const float* __restrict__ biasF, __half* __restrict__ out)
{
    __shared__ __half ks [KC * KSTR];   // [key][d]
    __shared__ __half vsT[32 * VSTR];   // [d][key]

    const int wi   = blockIdx.x;      // 0..63 : b*16 + wy*4 + wx
    const int head = blockIdx.y;
    const int b  = wi >> 4;
    const int wy = (wi >> 2) & 3;
    const int wx = wi & 3;
    const int t    = threadIdx.x;
    const int warp = t >> 5;
    const int lane = t & 31;
    const int gid  = lane >> 2;
    const int tig  = lane & 3;
    const int wq   = warp * 32;

    const int l8 = lane & 7;
    const int b3 = (lane >> 3) & 1;
    const int b4 = (lane >> 4) & 1;

    // ---- load Q fragments once (scaled, fp16, d padded to 32) ----
    uint32_t qf[2][2][4];
    #pragma unroll
    for (int mi = 0; mi < 2; mi++) {
        int iy = (wq + mi * 16) >> 4;
        int gy = wy * WS + iy;
        const __half* q0 = qh + ((size_t)(b * 4096 + gy * 64 + wx * WS + gid)) * C_DIM + head * DHEAD;
        const __half* q1 = qh + ((size_t)(b * 4096 + gy * 64 + wx * WS + gid + 8)) * C_DIM + head * DHEAD;
        const float sc = 0.18257418583505537f;  // 30^-0.5
        #pragma unroll
        for (int kd = 0; kd < 2; kd++) {
            int d0 = kd * 16 + 2 * tig;
            int d2 = d0 + 8;
            float2 f0 = __half22float2(*(const __half2*)(q0 + d0));
            float2 f1 = __half22float2(*(const __half2*)(q1 + d0));
            float2 f2 = (d2 < DHEAD) ? __half22float2(*(const __half2*)(q0 + d2))
                                     : make_float2(0.f, 0.f);
            float2 f3 = (d2 < DHEAD) ? __half22float2(*(const __half2*)(q1 + d2))
                                     : make_float2(0.f, 0.f);
            qf[mi][kd][0] = pack_h2(f0.x * sc, f0.y * sc);
            qf[mi][kd][1] = pack_h2(f1.x * sc, f1.y * sc);
            qf[mi][kd][2] = pack_h2(f2.x * sc, f2.y * sc);
            qf[mi][kd][3] = pack_h2(f3.x * sc, f3.y * sc);
        }
    }

    const float* bfh = biasF + (size_t)head * (72 * 16 * 128);
    const uint32_t ks_u  = smem_u32(ks);
    const uint32_t vsT_u = smem_u32(vsT);

    float l[2][2] = {{0.f, 0.f}, {0.f, 0.f}};
    float o[2][4][4];
    #pragma unroll
    for (int mi = 0; mi < 2; mi++)
        #pragma unroll
        for (int nj = 0; nj < 4; nj++)
            #pragma unroll
            for (int u = 0; u < 4; u++) o[mi][nj][u] = 0.f;

    for (int c0 = 0; c0 < NKEY; c0 += KC) {
        __syncthreads();
        for (int idx = t; idx < KC * 16; idx += 256) {
            int j  = idx >> 4;
            int d2 = idx & 15;
            int key = c0 + j;
            int jy = key / OWS;
            int jx = key - jy * OWS;
            int ky = wy * WS - 4 + jy;
            int kx = wx * WS - 4 + jx;
            __half2 kval = __floats2half2_rn(0.f, 0.f), vval = kval;
            if (d2 < 15 && (unsigned)ky < 64u && (unsigned)kx < 64u) {
                const __half* p = kvh + ((size_t)(b * 4096 + ky * 64 + kx)) * (2 * C_DIM)
                                      + head * DHEAD + 2 * d2;
                kval = *(const __half2*)p;
                vval = *(const __half2*)(p + C_DIM);
            }
            *(__half2*)&ks[j * KSTR + 2 * d2] = kval;
            vsT[(2 * d2) * VSTR + j]     = __low2half(vval);
            vsT[(2 * d2 + 1) * VSTR + j] = __high2half(vval);
        }
        __syncthreads();

        float la[2][2] = {{0.f, 0.f}, {0.f, 0.f}};

        #pragma unroll
        for (int u = 0; u < 4; u++) {
            float se[2][4], so[2][4];
            #pragma unroll
            for (int mi = 0; mi < 2; mi++)
                #pragma unroll
                for (int w = 0; w < 4; w++) { se[mi][w] = 0.f; so[mi][w] = 0.f; }

            #pragma unroll
            for (int kd = 0; kd < 2; kd++) {
                int keyrow = u * 16 + b4 * 8 + l8;
                int doff   = kd * 16 + b3 * 8;
                uint32_t r[4];
                ldsm_x4(r, ks_u + 2 * (keyrow * KSTR + doff));
                uint32_t be[2] = { r[0], r[1] };
                uint32_t bo[2] = { r[2], r[3] };
                #pragma unroll
                for (int mi = 0; mi < 2; mi++) {
                    mma_f16(se[mi], qf[mi][kd], be);
                    mma_f16(so[mi], qf[mi][kd], bo);
                }
            }

            int k8 = (c0 >> 3) + 2 * u;
            #pragma unroll
            for (int mi = 0; mi < 2; mi++) {
                int qblk = warp * 2 + mi;
                float4 bve = *(const float4*)(bfh + (((size_t)k8 * 16 + qblk) << 7) + (lane << 2));
                float4 bvo = *(const float4*)(bfh + (((size_t)(k8 + 1) * 16 + qblk) << 7) + (lane << 2));
                se[mi][0] = __expf(se[mi][0] + bve.x);
                se[mi][1] = __expf(se[mi][1] + bve.y);
                se[mi][2] = __expf(se[mi][2] + bve.z);
                se[mi][3] = __expf(se[mi][3] + bve.w);
                so[mi][0] = __expf(so[mi][0] + bvo.x);
                so[mi][1] = __expf(so[mi][1] + bvo.y);
                so[mi][2] = __expf(so[mi][2] + bvo.z);
                so[mi][3] = __expf(so[mi][3] + bvo.w);
                la[mi][0] += se[mi][0] + se[mi][1] + so[mi][0] + so[mi][1];
                la[mi][1] += se[mi][2] + se[mi][3] + so[mi][2] + so[mi][3];
            }

            uint32_t ap[2][4];
            #pragma unroll
            for (int mi = 0; mi < 2; mi++) {
                ap[mi][0] = pack_h2(se[mi][0], se[mi][1]);
                ap[mi][1] = pack_h2(se[mi][2], se[mi][3]);
                ap[mi][2] = pack_h2(so[mi][0], so[mi][1]);
                ap[mi][3] = pack_h2(so[mi][2], so[mi][3]);
            }

            uint32_t bvv[4][2];
            #pragma unroll
            for (int p = 0; p < 2; p++) {
                int drow   = (2 * p + b4) * 8 + l8;
                int keyoff = u * 16 + b3 * 8;
                uint32_t r[4];
                ldsm_x4(r, vsT_u + 2 * (drow * VSTR + keyoff));
                bvv[2 * p][0] = r[0]; bvv[2 * p][1] = r[1];
                bvv[2 * p + 1][0] = r[2]; bvv[2 * p + 1][1] = r[3];
            }
            #pragma unroll
            for (int nj = 0; nj < 4; nj++)
                #pragma unroll
                for (int mi = 0; mi < 2; mi++)
                    mma_f16(o[mi][nj], ap[mi], bvv[nj]);
        }

        #pragma unroll
        for (int mi = 0; mi < 2; mi++) {
            float la0 = la[mi][0], la1 = la[mi][1];
            la0 += __shfl_xor_sync(0xffffffffu, la0, 1);
            la0 += __shfl_xor_sync(0xffffffffu, la0, 2);
            la1 += __shfl_xor_sync(0xffffffffu, la1, 1);
            la1 += __shfl_xor_sync(0xffffffffu, la1, 2);
            l[mi][0] += la0; l[mi][1] += la1;
        }
    }

    #pragma unroll
    for (int mi = 0; mi < 2; mi++) {
        float inv0 = 1.f / l[mi][0];
        float inv1 = 1.f / l[mi][1];
        int iy = (wq + mi * 16) >> 4;
        int gy = wy * WS + iy;
        __half* o0 = out + ((size_t)(b * 4096 + gy * 64 + wx * WS + gid)) * KP + head * DHEAD;
        __half* o1 = out + ((size_t)(b * 4096 + gy * 64 + wx * WS + gid + 8)) * KP + head * DHEAD;
        #pragma unroll
        for (int nj = 0; nj < 4; nj++) {
            int d = nj * 8 + 2 * tig;
            if (d < DHEAD) {
                *(__half2*)(o0 + d) = __floats2half2_rn(o[mi][nj][0] * inv0, o[mi][nj][1] * inv0);
                *(__half2*)(o1 + d) = __floats2half2_rn(o[mi][nj][2] * inv1, o[mi][nj][3] * inv1);
            }
        }
    }
    if (head == 0) {
        int pix = b * 4096 + (wy * WS + (t >> 4)) * 64 + wx * WS + (t & 15);
        __half* pr = out + (size_t)pix * KP + C_DIM;
        __half2 z = __floats2half2_rn(0.f, 0.f);
        #pragma unroll
        for (int cc = 0; cc < 6; cc++) *(__half2*)(pr + 2 * cc) = z;
    }
}

// ---------------- launch --------------------------------------------------
extern "C" void kernel_launch(void* const* d_in, const int* in_sizes, int n_in,
                              void* d_out, int out_size)
{
    const float* x      = (const float*)d_in[0];
    const float* y      = (const float*)d_in[1];
    const float* n1g    = (const float*)d_in[2];
    const float* n1b    = (const float*)d_in[3];
    const float* kv_w   = (const float*)d_in[4];
    const float* kv_b   = (const float*)d_in[5];
    const float* q_w    = (const float*)d_in[6];
    const float* q_b    = (const float*)d_in[7];
    const float* rpb    = (const float*)d_in[8];
    const float* proj_w = (const float*)d_in[9];
    const float* proj_b = (const float*)d_in[10];
    const float* n2g    = (const float*)d_in[11];
    const float* n2b    = (const float*)d_in[12];
    const float* fc1_w  = (const float*)d_in[13];
    const float* fc1_b  = (const float*)d_in[14];
    const float* fc2_w  = (const float*)d_in[15];
    const float* fc2_b  = (const float*)d_in[16];
    const int*   rpi    = (const int*)d_in[17];
    float* outp = (float*)d_out;

    __half *xn, *yn, *ath, *xn2, *h1, *w16, *kvh, *qh, *xoh;
    float *biasp;
    cudaGetSymbolAddress((void**)&xn,    g_xn_h);
    cudaGetSymbolAddress((void**)&yn,    g_yn_h);
    cudaGetSymbolAddress((void**)&ath,   g_at_h);
    cudaGetSymbolAddress((void**)&xn2,   g_xn2_h);
    cudaGetSymbolAddress((void**)&h1,    g_h1_h);
    cudaGetSymbolAddress((void**)&w16,   g_w16);
    cudaGetSymbolAddress((void**)&kvh,   g_kv_h);
    cudaGetSymbolAddress((void**)&qh,    g_q_h);
    cudaGetSymbolAddress((void**)&xoh,   g_xo_h);
    cudaGetSymbolAddress((void**)&biasp, g_bias);

    const int loop_smem = (2 * ABUF_H + 2 * WBUF_H) * 2;   // 43008 bytes
    cudaFuncSetAttribute(qkv_gemm,        cudaFuncAttributeMaxDynamicSharedMemorySize, FULL_SMEM);
    cudaFuncSetAttribute(gemm_full<1,1>,  cudaFuncAttributeMaxDynamicSharedMemorySize, FULL_SMEM);
    cudaFuncSetAttribute(gemm_full<2,1>,  cudaFuncAttributeMaxDynamicSharedMemorySize, FULL_SMEM);
    cudaFuncSetAttribute(gemm_loop<3,0>,  cudaFuncAttributeMaxDynamicSharedMemorySize, loop_smem);

    // fused prologue: LN(x), LN(y), bias table, weight conversion
    prep_kernel<<<PREP_BLKS, 256>>>(x, y, n1g, n1b, xn, yn,
                                    rpi, rpb, biasp,
                                    kv_w, q_w, proj_w, fc1_w, fc2_w, w16);

    // kv + q projections (single-shot fp16 GEMM, BM=128 -> half outputs)
    qkv_gemm<<<dim3(9, M_ROWS / 128), 256, FULL_SMEM>>>(xn, yn, w16, kv_b, q_b, kvh, qh);

    // windowed attention (fp16 mma + ldmatrix, half output)
    attn_tc<<<dim3(64, NHEAD), 256>>>(qh, kvh, biasp, ath);

    // xo = attn @ proj_w^T + proj_b + x   (HALF out)
    gemm_full<1,1><<<dim3(3, M_ROWS / 128), 256, FULL_SMEM>>>(ath, w16 + W_PROJ, proj_b, x,
                                                              nullptr, xoh, C_DIM);

    // LN2 (half in -> half out)
    ln2_kernel<<<M_ROWS / 8, 256>>>(xoh, n2g, n2b, xn2);

    // h1 = gelu(xn2 @ fc1_w^T + fc1_b)  (half out)
    gemm_full<2,1><<<dim3(12, M_ROWS / 128), 256, FULL_SMEM>>>(xn2, w16 + W_FC1, fc1_b, nullptr,
                                                               nullptr, h1, 4 * C_DIM);

    // out = h1 @ fc2_w^T + fc2_b + xo(half)  (fp32 out, looped K=720)
    gemm_loop<3,0><<<dim3(3, M_ROWS / 128), 256, loop_smem>>>(h1, w16 + W_FC2, fc2_b, xoh,
                                                              outp, nullptr, C_DIM, 720);
}